// round 15
// baseline (speedup 1.0000x reference)
#include <cuda_runtime.h>
#include <cstdint>
#include <cstddef>

#define CN  2048
#define TOK 4096
#define KDIM 8192
#define NLOG 24

__device__ float g_xin [TOK * CN];
__device__ float g_wt  [CN * CN];     // W^T, tf32-rounded, [n][k]
__device__ float g_phit[32 * KDIM];   // phi^T, tf32-rounded, rows 24..31 zero
__device__ float g_coef[TOK * NLOG];

__device__ __forceinline__ uint32_t smem_u32(const void* p) {
    uint32_t a;
    asm("{ .reg .u64 t; cvta.to.shared.u64 t, %1; cvt.u32.u64 %0, t; }" : "=r"(a) : "l"(p));
    return a;
}
__device__ __forceinline__ float to_tf32(float v) {
    uint32_t r; asm("cvt.rna.tf32.f32 %0, %1;" : "=r"(r) : "f"(v));
    return __uint_as_float(r);
}
__device__ __forceinline__ void cp16(uint32_t s, const float* g) {
    asm volatile("cp.async.cg.shared.global [%0], [%1], 16;" :: "r"(s), "l"(g));
}
__device__ __forceinline__ void ldsm_x4(uint32_t addr, uint32_t& r0, uint32_t& r1,
                                        uint32_t& r2, uint32_t& r3) {
    asm volatile("ldmatrix.sync.aligned.m8n8.x4.shared.b16 {%0,%1,%2,%3}, [%4];"
        : "=r"(r0), "=r"(r1), "=r"(r2), "=r"(r3) : "r"(addr));
}
__device__ __forceinline__ void ldsm_x2(uint32_t addr, uint32_t& r0, uint32_t& r1) {
    asm volatile("ldmatrix.sync.aligned.m8n8.x2.shared.b16 {%0,%1}, [%2];"
        : "=r"(r0), "=r"(r1) : "r"(addr));
}
__device__ __forceinline__ void mma_tf32(float* c, const uint32_t* a, const uint32_t* b) {
    asm volatile(
        "mma.sync.aligned.m16n8k8.row.col.f32.tf32.tf32.f32 "
        "{%0,%1,%2,%3}, {%4,%5,%6,%7}, {%8,%9}, {%0,%1,%2,%3};"
        : "+f"(c[0]), "+f"(c[1]), "+f"(c[2]), "+f"(c[3])
        : "r"(a[0]), "r"(a[1]), "r"(a[2]), "r"(a[3]), "r"(b[0]), "r"(b[1]));
}

// ---------------- K1: W^T (tf32-rounded) ----------------
__global__ void k_transpose(const float* __restrict__ W) {
    __shared__ float t[32][33];
    int bx = blockIdx.x, by = blockIdx.y, tx = threadIdx.x, ty = threadIdx.y;
#pragma unroll
    for (int i = 0; i < 32; i += 8)
        t[ty + i][tx] = W[(size_t)(by * 32 + ty + i) * CN + bx * 32 + tx];
    __syncthreads();
#pragma unroll
    for (int i = 0; i < 32; i += 8)
        g_wt[(size_t)(bx * 32 + ty + i) * CN + by * 32 + tx] = to_tf32(t[tx][ty + i]);
}

// ---------------- K1b: phi^T (tf32-rounded, padded to 32 rows) ----------------
__global__ void k_phiprep(const float* __restrict__ phi) {
    __shared__ float t[32][25];
    const int k0 = blockIdx.x * 32;
    const int tx = threadIdx.x, ty = threadIdx.y;   // 32 x 8
#pragma unroll
    for (int jj = 0; jj < 3; jj++) {
        int j = ty + jj * 8;
        t[tx][j] = phi[(size_t)(k0 + tx) * NLOG + j];
    }
    __syncthreads();
#pragma unroll
    for (int jj = 0; jj < 4; jj++) {
        int j = ty + jj * 8;
        float v = (j < NLOG) ? to_tf32(t[tx][j]) : 0.f;
        g_phit[(size_t)j * KDIM + k0 + tx] = v;
    }
}

// ---------------- sink helper ----------------
#define FINISH_TOKEN(dst, A, rr) do {                                         \
    float L[NLOG];                                                            \
    _Pragma("unroll") for (int j = 0; j < NLOG; j++) L[j] = A[j] * (rr) + bias[j]; \
    _Pragma("unroll") for (int h = 0; h < 4; h++) {                           \
        (dst)[h]     = 1.0f / (1.0f + expf(-ap * L[h])) + 1e-4f;              \
        (dst)[4 + h] = 2.0f / (1.0f + expf(-aq * L[4 + h]));                  \
    }                                                                         \
    float m[16];                                                              \
    _Pragma("unroll") for (int i = 0; i < 16; i++) m[i] = expf(ar * L[8 + i]);\
    _Pragma("unroll") for (int it = 0; it < 8; it++) {                        \
        _Pragma("unroll") for (int o = 0; o < 4; o++) {                       \
            float inv = 1.0f / (m[o*4] + m[o*4+1] + m[o*4+2] + m[o*4+3] + 1e-6f); \
            m[o*4] *= inv; m[o*4+1] *= inv; m[o*4+2] *= inv; m[o*4+3] *= inv; \
        }                                                                     \
        _Pragma("unroll") for (int i = 0; i < 4; i++) {                       \
            float inv = 1.0f / (m[i] + m[4+i] + m[8+i] + m[12+i] + 1e-6f);    \
            m[i] *= inv; m[4+i] *= inv; m[8+i] *= inv; m[12+i] *= inv;        \
        }                                                                     \
    }                                                                         \
    _Pragma("unroll") for (int i = 0; i < 16; i++) (dst)[8 + i] = m[i];       \
} while (0)

// ---------------- K2: logits via tensor cores (wide 128-k stages) -----------
static constexpr int LG_ROW   = 132;
static constexpr int LG_STF   = 32 * LG_ROW;
static constexpr int LG_STAGE = 2 * LG_STF;
static constexpr uint32_t LG_SMEM = 3u * LG_STAGE * 4u;  // 101376 B
static constexpr int LG_NKT = KDIM / 128;

__global__ __launch_bounds__(256) void k_logits(const float* __restrict__ x,
                                                const float* __restrict__ bias,
                                                const float* __restrict__ a_pre,
                                                const float* __restrict__ a_post,
                                                const float* __restrict__ a_res) {
    extern __shared__ __align__(16) float lsm[];
    __shared__ float Lbuf[4][32][25];
    __shared__ float ssm[32];
    const int tid = threadIdx.x, lane = tid & 31, wid = tid >> 5;
    const int mt = wid & 1, kq = wid >> 1;
    const int m0 = blockIdx.x * 32;
    const int row = tid >> 3, cs = tid & 7;
    const float* xrow = x + (size_t)(m0 + row) * KDIM + cs * 4;
    const float* prow = g_phit + (size_t)row * KDIM + cs * 4;

    auto load_stage = [&](int kc, int st) {
        float* A = lsm + st * LG_STAGE;
        float* B = A + LG_STF;
#pragma unroll
        for (int i = 0; i < 4; i++) {
            cp16(smem_u32(A + row * LG_ROW + i * 32 + cs * 4), xrow + kc * 128 + i * 32);
            cp16(smem_u32(B + row * LG_ROW + i * 32 + cs * 4), prow + kc * 128 + i * 32);
        }
        asm volatile("cp.async.commit_group;" ::: "memory");
    };

    load_stage(0, 0);
    load_stage(1, 1);

    const uint32_t a_lane = (uint32_t)((((lane & 7) | ((lane >> 1) & 8)) * LG_ROW +
                                        ((lane >> 3) & 1) * 4) * 4);
    const uint32_t b_lane = (uint32_t)(((lane & 7) * LG_ROW + ((lane >> 3) & 1) * 4) * 4);

    float c[3][4];
#pragma unroll
    for (int i = 0; i < 3; i++)
#pragma unroll
        for (int j = 0; j < 4; j++) c[i][j] = 0.f;
    float ss = 0.f;

    for (int kt = 0; kt < LG_NKT; kt++) {
        const int st = kt % 3;
        float* A = lsm + st * LG_STAGE;
        asm volatile("cp.async.wait_group 1;" ::: "memory");
        __syncthreads();
#pragma unroll
        for (int i = 0; i < 4; i++) {
            float4* p = (float4*)(A + row * LG_ROW + i * 32 + cs * 4);
            float4 v = *p;
            ss += v.x * v.x + v.y * v.y + v.z * v.z + v.w * v.w;
            v.x = to_tf32(v.x); v.y = to_tf32(v.y); v.z = to_tf32(v.z); v.w = to_tf32(v.w);
            *p = v;
        }
        __syncthreads();
        if (kt + 2 < LG_NKT) load_stage(kt + 2, (kt + 2) % 3);
        else asm volatile("cp.async.commit_group;" ::: "memory");

        const uint32_t Abase = smem_u32(A) + (uint32_t)(mt * 16 * LG_ROW) * 4u + a_lane +
                               (uint32_t)(kq * 32 * 4);
        const uint32_t Bbase = smem_u32(A + LG_STF) + b_lane + (uint32_t)(kq * 32 * 4);
#pragma unroll
        for (int s = 0; s < 4; s++) {
            uint32_t a4[4], b2[3][2];
            {
                uint32_t r0, r1, r2, r3;
                ldsm_x4(Abase + (uint32_t)(s * 32), r0, r1, r2, r3);
                a4[0] = r0; a4[1] = r2; a4[2] = r1; a4[3] = r3;
            }
#pragma unroll
            for (int nt = 0; nt < 3; nt++)
                ldsm_x2(Bbase + (uint32_t)(nt * 8 * LG_ROW * 4 + s * 32), b2[nt][0], b2[nt][1]);
#pragma unroll
            for (int nt = 0; nt < 3; nt++)
                mma_tf32(c[nt], a4, b2[nt]);
        }
    }

    ss += __shfl_down_sync(~0u, ss, 4);
    ss += __shfl_down_sync(~0u, ss, 2);
    ss += __shfl_down_sync(~0u, ss, 1);
    if (cs == 0) ssm[row] = ss;

    {
        const int lr = lane >> 2, lc = lane & 3;
#pragma unroll
        for (int nt = 0; nt < 3; nt++) {
            Lbuf[kq][mt * 16 + lr][nt * 8 + lc * 2]         = c[nt][0];
            Lbuf[kq][mt * 16 + lr][nt * 8 + lc * 2 + 1]     = c[nt][1];
            Lbuf[kq][mt * 16 + lr + 8][nt * 8 + lc * 2]     = c[nt][2];
            Lbuf[kq][mt * 16 + lr + 8][nt * 8 + lc * 2 + 1] = c[nt][3];
        }
    }
    __syncthreads();

    if (tid < 32) {
        float A[NLOG];
#pragma unroll
        for (int j = 0; j < NLOG; j++)
            A[j] = Lbuf[0][tid][j] + Lbuf[1][tid][j] + Lbuf[2][tid][j] + Lbuf[3][tid][j];
        const float ap = a_pre[0], aq = a_post[0], ar = a_res[0];
        const float r = rsqrtf(ssm[tid] * (1.0f / (float)KDIM) + 1e-6f);
        FINISH_TOKEN(g_coef + (size_t)(m0 + tid) * NLOG, A, r);
    }
}

// ---------------- K3: x_in (tf32-rounded) ----------------
__global__ __launch_bounds__(256) void k_xin(const float* __restrict__ x) {
    const int t = blockIdx.x >> 1;
    const int c = ((blockIdx.x & 1) * 256 + threadIdx.x) * 4;
    __shared__ float hp[4];
    if (threadIdx.x < 4) hp[threadIdx.x] = g_coef[(size_t)t * NLOG + threadIdx.x];
    __syncthreads();
    const float* xb = x + (size_t)t * KDIM + c;
    float4 v0 = *(const float4*)xb;
    float4 v1 = *(const float4*)(xb + CN);
    float4 v2 = *(const float4*)(xb + 2 * CN);
    float4 v3 = *(const float4*)(xb + 3 * CN);
    float h0 = hp[0], h1 = hp[1], h2 = hp[2], h3 = hp[3];
    float4 s;
    s.x = to_tf32(h0 * v0.x + h1 * v1.x + h2 * v2.x + h3 * v3.x);
    s.y = to_tf32(h0 * v0.y + h1 * v1.y + h2 * v2.y + h3 * v3.y);
    s.z = to_tf32(h0 * v0.z + h1 * v1.z + h2 * v2.z + h3 * v3.z);
    s.w = to_tf32(h0 * v0.w + h1 * v1.w + h2 * v2.w + h3 * v3.w);
    *(float4*)(g_xin + (size_t)t * CN + c) = s;
}

// ---------------- K4: GEMM (256x128 tile, k=64) + fused output ----------------
static constexpr int GM_ROW   = 68;                       // 64 + 4 pad floats
static constexpr int GM_ASTF  = 256 * GM_ROW;             // 17408 fl
static constexpr int GM_BSTF  = 128 * GM_ROW;             // 8704 fl
static constexpr int GM_STAGE = GM_ASTF + GM_BSTF;        // 26112 fl
static constexpr uint32_t GEMM_SMEM = 2u * GM_STAGE * 4u; // 208896 B
static constexpr int GM_NKT = CN / 64;                    // 32

__global__ __launch_bounds__(256) void k_gemm(const float* __restrict__ x,
                                              const float* __restrict__ Wb,
                                              float* __restrict__ out) {
    extern __shared__ __align__(16) float smf[];
    const int tid = threadIdx.x, lane = tid & 31, wid = tid >> 5;
    const int wm = wid >> 1, wn = wid & 1;          // 4(m) x 2(n), warp tile 64x64
    const int m0 = blockIdx.y * 256, n0 = blockIdx.x * 128;
    const int lr = lane >> 2, lc = lane & 3;

    auto load_stage = [&](int kc, int st) {
        float* base = smf + st * GM_STAGE;
        const int k0 = kc * 64;
#pragma unroll
        for (int i = 0; i < 16; i++) {              // A: 256 rows x 64 fl
            int seg = tid + 256 * i, r = seg >> 4, cs = seg & 15;
            cp16(smem_u32(base + r * GM_ROW + cs * 4),
                 g_xin + (size_t)(m0 + r) * CN + k0 + cs * 4);
        }
        float* bb = base + GM_ASTF;
#pragma unroll
        for (int i = 0; i < 8; i++) {               // B: 128 rows x 64 fl
            int seg = tid + 256 * i, r = seg >> 4, cs = seg & 15;
            cp16(smem_u32(bb + r * GM_ROW + cs * 4),
                 g_wt + (size_t)(n0 + r) * CN + k0 + cs * 4);
        }
        asm volatile("cp.async.commit_group;" ::: "memory");
    };

    load_stage(0, 0);
    load_stage(1, 1);

    const uint32_t a_lane = (uint32_t)((((lane & 7) | ((lane >> 1) & 8)) * GM_ROW +
                                        ((lane >> 3) & 1) * 4) * 4);
    const uint32_t b_lane4 = (uint32_t)(((lane & 7) * GM_ROW + ((lane >> 3) & 1) * 4 +
                                         ((lane >> 4) & 1) * (8 * GM_ROW)) * 4);

    float c[4][8][4];
#pragma unroll
    for (int i = 0; i < 4; i++)
#pragma unroll
        for (int j = 0; j < 8; j++)
#pragma unroll
            for (int k = 0; k < 4; k++) c[i][j][k] = 0.f;

    for (int kt = 0; kt < GM_NKT; kt++) {
        asm volatile("cp.async.wait_group 1;" ::: "memory");
        __syncthreads();

        const uint32_t sa = smem_u32(smf + (kt & 1) * GM_STAGE);
        const uint32_t abase = sa + (uint32_t)(wm * 64 * GM_ROW) * 4u + a_lane;
        const uint32_t bbase = sa + (uint32_t)(GM_ASTF + wn * 64 * GM_ROW) * 4u + b_lane4;
#pragma unroll
        for (int s0 = 0; s0 < 8; s0++) {
            const int s = (s0 + wid) & 7;           // de-burst rotation
            uint32_t a4[4][4], b2[8][2];
#pragma unroll
            for (int mt = 0; mt < 4; mt++) {
                uint32_t r0, r1, r2, r3;
                ldsm_x4(abase + (uint32_t)(mt * 16 * GM_ROW * 4 + s * 32), r0, r1, r2, r3);
                a4[mt][0] = r0; a4[mt][1] = r2; a4[mt][2] = r1; a4[mt][3] = r3;
            }
#pragma unroll
            for (int p = 0; p < 4; p++) {
                uint32_t r0, r1, r2, r3;
                ldsm_x4(bbase + (uint32_t)(p * 16 * GM_ROW * 4 + s * 32), r0, r1, r2, r3);
                b2[2 * p][0] = r0; b2[2 * p][1] = r1;
                b2[2 * p + 1][0] = r2; b2[2 * p + 1][1] = r3;
            }
#pragma unroll
            for (int mt = 0; mt < 4; mt++)
#pragma unroll
                for (int nt = 0; nt < 8; nt++)
                    mma_tf32(c[mt][nt], a4[mt], b2[nt]);
        }
        __syncthreads();
        if (kt + 2 < GM_NKT) load_stage(kt + 2, kt & 1);
        else asm volatile("cp.async.commit_group;" ::: "memory");
    }

    // stage this CTA's coefs (256 tokens x 24 fl) into smem
    {
        float4* cs4 = (float4*)smf;
        const float4* gc4 = (const float4*)(g_coef + (size_t)m0 * NLOG);
        for (int i = tid; i < 256 * NLOG / 4; i += 256) cs4[i] = gc4[i];
    }
    __syncthreads();

    // fused output epilogue
#pragma unroll
    for (int mt = 0; mt < 4; mt++) {
#pragma unroll
        for (int half = 0; half < 2; half++) {
            const int lrow = wm * 64 + mt * 16 + lr + half * 8;
            const int t = m0 + lrow;
            const float* cc = smf + lrow * NLOG;
            float R[16];
#pragma unroll
            for (int i = 0; i < 16; i++) R[i] = cc[8 + i];
            const float hp0 = cc[4], hp1 = cc[5], hp2 = cc[6], hp3 = cc[7];
            const float* xb = x + (size_t)t * KDIM;
            float* ob = out + (size_t)t * KDIM;
#pragma unroll
            for (int nt = 0; nt < 8; nt++) {
                const int col = n0 + wn * 64 + nt * 8 + lc * 2;
                const float f0 = c[mt][nt][half * 2]     + Wb[col];
                const float f1 = c[mt][nt][half * 2 + 1] + Wb[col + 1];
                float2 xv0 = *(const float2*)(xb + col);
                float2 xv1 = *(const float2*)(xb + CN + col);
                float2 xv2 = *(const float2*)(xb + 2 * CN + col);
                float2 xv3 = *(const float2*)(xb + 3 * CN + col);
                const float hps[4] = {hp0, hp1, hp2, hp3};
#pragma unroll
                for (int o = 0; o < 4; o++) {
                    float2 r;
                    r.x = R[o*4]*xv0.x + R[o*4+1]*xv1.x + R[o*4+2]*xv2.x + R[o*4+3]*xv3.x + hps[o]*f0;
                    r.y = R[o*4]*xv0.y + R[o*4+1]*xv1.y + R[o*4+2]*xv2.y + R[o*4+3]*xv3.y + hps[o]*f1;
                    *(float2*)(ob + o * CN + col) = r;
                }
            }
        }
    }
}

extern "C" void kernel_launch(void* const* d_in, const int* in_sizes, int n_in,
                              void* d_out, int out_size) {
    const float* x      = (const float*)d_in[0];
    const float* phi    = (const float*)d_in[1];
    const float* b      = (const float*)d_in[2];
    const float* a_pre  = (const float*)d_in[3];
    const float* a_post = (const float*)d_in[4];
    const float* a_res  = (const float*)d_in[5];
    const float* W      = (const float*)d_in[6];
    const float* Wb     = (const float*)d_in[7];
    float* out = (float*)d_out;

    cudaFuncSetAttribute(k_gemm, cudaFuncAttributeMaxDynamicSharedMemorySize, GEMM_SMEM);
    cudaFuncSetAttribute(k_logits, cudaFuncAttributeMaxDynamicSharedMemorySize, LG_SMEM);

    k_transpose<<<dim3(CN / 32, CN / 32), dim3(32, 8)>>>(W);
    k_phiprep<<<KDIM / 32, dim3(32, 8)>>>(phi);
    k_logits<<<TOK / 32, 256, LG_SMEM>>>(x, b, a_pre, a_post, a_res);
    k_xin<<<TOK * 2, 256>>>(x);
    k_gemm<<<dim3(CN / 128, TOK / 256), 256, GEMM_SMEM>>>(x, Wb, out);
}

// round 16
// speedup vs baseline: 1.1542x; 1.1542x over previous
#include <cuda_runtime.h>
#include <cstdint>
#include <cstddef>

#define CN  2048
#define TOK 4096
#define KDIM 8192
#define NLOG 24

__device__ float g_xin [TOK * CN];
__device__ float g_wt  [CN * CN];     // W^T, tf32-rounded, [n][k]
__device__ float g_phit[32 * KDIM];   // phi^T, tf32-rounded, rows 24..31 zero
__device__ float g_coef[TOK * NLOG];

__device__ __forceinline__ uint32_t smem_u32(const void* p) {
    uint32_t a;
    asm("{ .reg .u64 t; cvta.to.shared.u64 t, %1; cvt.u32.u64 %0, t; }" : "=r"(a) : "l"(p));
    return a;
}
__device__ __forceinline__ float to_tf32(float v) {
    uint32_t r; asm("cvt.rna.tf32.f32 %0, %1;" : "=r"(r) : "f"(v));
    return __uint_as_float(r);
}
__device__ __forceinline__ uint32_t to_tf32_u(uint32_t v) {
    uint32_t r; asm("cvt.rna.tf32.f32 %0, %1;" : "=r"(r) : "f"(__uint_as_float(v)));
    return r;
}
__device__ __forceinline__ void cp16(uint32_t s, const float* g) {
    asm volatile("cp.async.cg.shared.global [%0], [%1], 16;" :: "r"(s), "l"(g));
}
__device__ __forceinline__ void ldsm_x4(uint32_t addr, uint32_t& r0, uint32_t& r1,
                                        uint32_t& r2, uint32_t& r3) {
    asm volatile("ldmatrix.sync.aligned.m8n8.x4.shared.b16 {%0,%1,%2,%3}, [%4];"
        : "=r"(r0), "=r"(r1), "=r"(r2), "=r"(r3) : "r"(addr));
}
__device__ __forceinline__ void ldsm_x2(uint32_t addr, uint32_t& r0, uint32_t& r1) {
    asm volatile("ldmatrix.sync.aligned.m8n8.x2.shared.b16 {%0,%1}, [%2];"
        : "=r"(r0), "=r"(r1) : "r"(addr));
}
__device__ __forceinline__ void mma_tf32(float* c, const uint32_t* a, const uint32_t* b) {
    asm volatile(
        "mma.sync.aligned.m16n8k8.row.col.f32.tf32.tf32.f32 "
        "{%0,%1,%2,%3}, {%4,%5,%6,%7}, {%8,%9}, {%0,%1,%2,%3};"
        : "+f"(c[0]), "+f"(c[1]), "+f"(c[2]), "+f"(c[3])
        : "r"(a[0]), "r"(a[1]), "r"(a[2]), "r"(a[3]), "r"(b[0]), "r"(b[1]));
}

// ---------------- K1: W^T (tf32-rounded) ----------------
__global__ void k_transpose(const float* __restrict__ W) {
    __shared__ float t[32][33];
    int bx = blockIdx.x, by = blockIdx.y, tx = threadIdx.x, ty = threadIdx.y;
#pragma unroll
    for (int i = 0; i < 32; i += 8)
        t[ty + i][tx] = W[(size_t)(by * 32 + ty + i) * CN + bx * 32 + tx];
    __syncthreads();
#pragma unroll
    for (int i = 0; i < 32; i += 8)
        g_wt[(size_t)(bx * 32 + ty + i) * CN + by * 32 + tx] = to_tf32(t[tx][ty + i]);
}

// ---------------- K1b: phi^T (tf32-rounded, padded to 32 rows) ----------------
__global__ void k_phiprep(const float* __restrict__ phi) {
    __shared__ float t[32][25];
    const int k0 = blockIdx.x * 32;
    const int tx = threadIdx.x, ty = threadIdx.y;   // 32 x 8
#pragma unroll
    for (int jj = 0; jj < 3; jj++) {
        int j = ty + jj * 8;
        t[tx][j] = phi[(size_t)(k0 + tx) * NLOG + j];
    }
    __syncthreads();
#pragma unroll
    for (int jj = 0; jj < 4; jj++) {
        int j = ty + jj * 8;
        float v = (j < NLOG) ? to_tf32(t[tx][j]) : 0.f;
        g_phit[(size_t)j * KDIM + k0 + tx] = v;
    }
}

// ---------------- sink helper ----------------
#define FINISH_TOKEN(dst, A, rr) do {                                         \
    float L[NLOG];                                                            \
    _Pragma("unroll") for (int j = 0; j < NLOG; j++) L[j] = A[j] * (rr) + bias[j]; \
    _Pragma("unroll") for (int h = 0; h < 4; h++) {                           \
        (dst)[h]     = 1.0f / (1.0f + expf(-ap * L[h])) + 1e-4f;              \
        (dst)[4 + h] = 2.0f / (1.0f + expf(-aq * L[4 + h]));                  \
    }                                                                         \
    float m[16];                                                              \
    _Pragma("unroll") for (int i = 0; i < 16; i++) m[i] = expf(ar * L[8 + i]);\
    _Pragma("unroll") for (int it = 0; it < 8; it++) {                        \
        _Pragma("unroll") for (int o = 0; o < 4; o++) {                       \
            float inv = 1.0f / (m[o*4] + m[o*4+1] + m[o*4+2] + m[o*4+3] + 1e-6f); \
            m[o*4] *= inv; m[o*4+1] *= inv; m[o*4+2] *= inv; m[o*4+3] *= inv; \
        }                                                                     \
        _Pragma("unroll") for (int i = 0; i < 4; i++) {                       \
            float inv = 1.0f / (m[i] + m[4+i] + m[8+i] + m[12+i] + 1e-6f);    \
            m[i] *= inv; m[4+i] *= inv; m[8+i] *= inv; m[12+i] *= inv;        \
        }                                                                     \
    }                                                                         \
    _Pragma("unroll") for (int i = 0; i < 16; i++) (dst)[8 + i] = m[i];       \
} while (0)

// ---------------- K2: logits via tensor cores (register-rounded A) ----------
static constexpr int LG_ROW   = 132;
static constexpr int LG_STF   = 32 * LG_ROW;
static constexpr int LG_STAGE = 2 * LG_STF;
static constexpr uint32_t LG_SMEM = 3u * LG_STAGE * 4u;  // 101376 B
static constexpr int LG_NKT = KDIM / 128;

__global__ __launch_bounds__(256) void k_logits(const float* __restrict__ x,
                                                const float* __restrict__ bias,
                                                const float* __restrict__ a_pre,
                                                const float* __restrict__ a_post,
                                                const float* __restrict__ a_res) {
    extern __shared__ __align__(16) float lsm[];
    __shared__ float Lbuf[4][32][25];
    __shared__ float ssp[4][32];
    const int tid = threadIdx.x, lane = tid & 31, wid = tid >> 5;
    const int mt = wid & 1, kq = wid >> 1;
    const int m0 = blockIdx.x * 32;
    const int row = tid >> 3, cs = tid & 7;
    const float* xrow = x + (size_t)(m0 + row) * KDIM + cs * 4;
    const float* prow = g_phit + (size_t)row * KDIM + cs * 4;

    auto load_stage = [&](int kc, int st) {
        float* A = lsm + st * LG_STAGE;
        float* B = A + LG_STF;
#pragma unroll
        for (int i = 0; i < 4; i++) {
            cp16(smem_u32(A + row * LG_ROW + i * 32 + cs * 4), xrow + kc * 128 + i * 32);
            cp16(smem_u32(B + row * LG_ROW + i * 32 + cs * 4), prow + kc * 128 + i * 32);
        }
        asm volatile("cp.async.commit_group;" ::: "memory");
    };

    load_stage(0, 0);
    load_stage(1, 1);

    const uint32_t a_lane = (uint32_t)((((lane & 7) | ((lane >> 1) & 8)) * LG_ROW +
                                        ((lane >> 3) & 1) * 4) * 4);
    const uint32_t b_lane = (uint32_t)(((lane & 7) * LG_ROW + ((lane >> 3) & 1) * 4) * 4);

    float c[3][4];
#pragma unroll
    for (int i = 0; i < 3; i++)
#pragma unroll
        for (int j = 0; j < 4; j++) c[i][j] = 0.f;
    float ss0 = 0.f, ss1 = 0.f;   // rows lr and lr+8 of this warp's m-block

    for (int kt = 0; kt < LG_NKT; kt++) {
        const int st = kt % 3;
        float* A = lsm + st * LG_STAGE;
        asm volatile("cp.async.wait_group 1;" ::: "memory");
        __syncthreads();
        if (kt + 2 < LG_NKT) load_stage(kt + 2, (kt + 2) % 3);
        else asm volatile("cp.async.commit_group;" ::: "memory");

        const uint32_t Abase = smem_u32(A) + (uint32_t)(mt * 16 * LG_ROW) * 4u + a_lane +
                               (uint32_t)(kq * 32 * 4);
        const uint32_t Bbase = smem_u32(A + LG_STF) + b_lane + (uint32_t)(kq * 32 * 4);
#pragma unroll
        for (int s = 0; s < 4; s++) {
            uint32_t a4[4], b2[3][2];
            {
                uint32_t r0, r1, r2, r3;
                ldsm_x4(Abase + (uint32_t)(s * 32), r0, r1, r2, r3);
                a4[0] = r0; a4[1] = r2; a4[2] = r1; a4[3] = r3;
            }
            // exact x^2 accumulation (rows: a4[0],a4[2] -> lr; a4[1],a4[3] -> lr+8)
            {
                float e0 = __uint_as_float(a4[0]), e1 = __uint_as_float(a4[1]);
                float e2 = __uint_as_float(a4[2]), e3 = __uint_as_float(a4[3]);
                ss0 += e0 * e0 + e2 * e2;
                ss1 += e1 * e1 + e3 * e3;
            }
            // round A fragments to tf32 (rna) in registers
            a4[0] = to_tf32_u(a4[0]); a4[1] = to_tf32_u(a4[1]);
            a4[2] = to_tf32_u(a4[2]); a4[3] = to_tf32_u(a4[3]);
#pragma unroll
            for (int nt = 0; nt < 3; nt++)
                ldsm_x2(Bbase + (uint32_t)(nt * 8 * LG_ROW * 4 + s * 32), b2[nt][0], b2[nt][1]);
#pragma unroll
            for (int nt = 0; nt < 3; nt++)
                mma_tf32(c[nt], a4, b2[nt]);
        }
    }

    // reduce ss over the 4 lanes sharing a row (lane = lr*4 + lc)
    ss0 += __shfl_down_sync(~0u, ss0, 2); ss0 += __shfl_down_sync(~0u, ss0, 1);
    ss1 += __shfl_down_sync(~0u, ss1, 2); ss1 += __shfl_down_sync(~0u, ss1, 1);
    {
        const int lr = lane >> 2, lc = lane & 3;
        if (lc == 0) {
            ssp[kq][mt * 16 + lr]     = ss0;
            ssp[kq][mt * 16 + lr + 8] = ss1;
        }
#pragma unroll
        for (int nt = 0; nt < 3; nt++) {
            Lbuf[kq][mt * 16 + lr][nt * 8 + lc * 2]         = c[nt][0];
            Lbuf[kq][mt * 16 + lr][nt * 8 + lc * 2 + 1]     = c[nt][1];
            Lbuf[kq][mt * 16 + lr + 8][nt * 8 + lc * 2]     = c[nt][2];
            Lbuf[kq][mt * 16 + lr + 8][nt * 8 + lc * 2 + 1] = c[nt][3];
        }
    }
    __syncthreads();

    if (tid < 32) {
        float A[NLOG];
#pragma unroll
        for (int j = 0; j < NLOG; j++)
            A[j] = Lbuf[0][tid][j] + Lbuf[1][tid][j] + Lbuf[2][tid][j] + Lbuf[3][tid][j];
        const float ap = a_pre[0], aq = a_post[0], ar = a_res[0];
        const float sst = ssp[0][tid] + ssp[1][tid] + ssp[2][tid] + ssp[3][tid];
        const float r = rsqrtf(sst * (1.0f / (float)KDIM) + 1e-6f);
        FINISH_TOKEN(g_coef + (size_t)(m0 + tid) * NLOG, A, r);
    }
}

// ---------------- K3: x_in (tf32-rounded) ----------------
__global__ __launch_bounds__(256) void k_xin(const float* __restrict__ x) {
    const int t = blockIdx.x >> 1;
    const int c = ((blockIdx.x & 1) * 256 + threadIdx.x) * 4;
    __shared__ float hp[4];
    if (threadIdx.x < 4) hp[threadIdx.x] = g_coef[(size_t)t * NLOG + threadIdx.x];
    __syncthreads();
    const float* xb = x + (size_t)t * KDIM + c;
    float4 v0 = *(const float4*)xb;
    float4 v1 = *(const float4*)(xb + CN);
    float4 v2 = *(const float4*)(xb + 2 * CN);
    float4 v3 = *(const float4*)(xb + 3 * CN);
    float h0 = hp[0], h1 = hp[1], h2 = hp[2], h3 = hp[3];
    float4 s;
    s.x = to_tf32(h0 * v0.x + h1 * v1.x + h2 * v2.x + h3 * v3.x);
    s.y = to_tf32(h0 * v0.y + h1 * v1.y + h2 * v2.y + h3 * v3.y);
    s.z = to_tf32(h0 * v0.z + h1 * v1.z + h2 * v2.z + h3 * v3.z);
    s.w = to_tf32(h0 * v0.w + h1 * v1.w + h2 * v2.w + h3 * v3.w);
    *(float4*)(g_xin + (size_t)t * CN + c) = s;
}

// ---------------- K4: GEMM + fused output (R14 proven config) ----------------
static constexpr int ST_FLOATS = 9216;
static constexpr int B_OFF     = 4608;
static constexpr uint32_t GEMM_SMEM = 3u * ST_FLOATS * 4u;   // 110592 B
static constexpr int NKCH = CN / 32;

__global__ __launch_bounds__(256, 2) void k_gemm(const float* __restrict__ x,
                                                 const float* __restrict__ Wb,
                                                 float* __restrict__ out) {
    extern __shared__ __align__(16) float smf[];
    const uint32_t sbase = smem_u32(smf);
    const int tid = threadIdx.x, lane = tid & 31, wid = tid >> 5;
    const int wm = wid >> 2, wn = wid & 3;
    const int srot = wid & 3;
    const int m0 = blockIdx.y * 128, n0 = blockIdx.x * 128;
    const int lr = lane >> 2, lc = lane & 3;

    auto load_stage = [&](int kc, int st) {
        const int k0 = kc * 32;
        const uint32_t sa = sbase + (uint32_t)(st * ST_FLOATS) * 4u;
#pragma unroll
        for (int i = 0; i < 4; i++) {
            int seg = tid + 256 * i, r = seg >> 3, cs = seg & 7;
            cp16(sa + (uint32_t)(r * 36 + cs * 4) * 4u,
                 g_xin + (size_t)(m0 + r) * CN + k0 + cs * 4);
        }
        const uint32_t sb = sa + B_OFF * 4u;
#pragma unroll
        for (int i = 0; i < 4; i++) {
            int seg = tid + 256 * i, r = seg >> 3, cs = seg & 7;
            cp16(sb + (uint32_t)(r * 36 + cs * 4) * 4u,
                 g_wt + (size_t)(n0 + r) * CN + k0 + cs * 4);
        }
        asm volatile("cp.async.commit_group;" ::: "memory");
    };

    load_stage(0, 0);
    load_stage(1, 1);

    const uint32_t a_lane = (uint32_t)((((lane & 7) | ((lane >> 1) & 8)) * 36 +
                                        ((lane >> 3) & 1) * 4) * 4);
    const uint32_t b_lane4 = (uint32_t)(((lane & 7) * 36 + ((lane >> 3) & 1) * 4 +
                                         ((lane >> 4) & 1) * (8 * 36)) * 4);

    float c[4][4][4];
#pragma unroll
    for (int i = 0; i < 4; i++)
#pragma unroll
        for (int j = 0; j < 4; j++)
#pragma unroll
            for (int k = 0; k < 4; k++) c[i][j][k] = 0.f;

    for (int kt = 0; kt < NKCH; kt++) {
        asm volatile("cp.async.wait_group 1;" ::: "memory");
        __syncthreads();
        if (kt + 2 < NKCH) load_stage(kt + 2, (kt + 2) % 3);
        else asm volatile("cp.async.commit_group;" ::: "memory");

        const uint32_t sa = sbase + (uint32_t)((kt % 3) * ST_FLOATS) * 4u;
        const uint32_t abase = sa + (uint32_t)(wm * 64 * 36) * 4u + a_lane;
        const uint32_t bbase = sa + (uint32_t)(B_OFF + wn * 32 * 36) * 4u + b_lane4;
#pragma unroll
        for (int s0 = 0; s0 < 4; s0++) {
            const int s = (s0 + srot) & 3;
            uint32_t a4[4][4], b2[4][2];
#pragma unroll
            for (int mt = 0; mt < 4; mt++) {
                uint32_t r0, r1, r2, r3;
                ldsm_x4(abase + (uint32_t)(mt * 16 * 36 * 4 + s * 32), r0, r1, r2, r3);
                a4[mt][0] = r0; a4[mt][1] = r2; a4[mt][2] = r1; a4[mt][3] = r3;
            }
#pragma unroll
            for (int p = 0; p < 2; p++) {
                uint32_t r0, r1, r2, r3;
                ldsm_x4(bbase + (uint32_t)(p * 16 * 36 * 4 + s * 32), r0, r1, r2, r3);
                b2[2 * p][0] = r0; b2[2 * p][1] = r1;
                b2[2 * p + 1][0] = r2; b2[2 * p + 1][1] = r3;
            }
#pragma unroll
            for (int mt = 0; mt < 4; mt++)
#pragma unroll
                for (int nt = 0; nt < 4; nt++)
                    mma_tf32(c[mt][nt], a4[mt], b2[nt]);
        }
    }

    __syncthreads();
    {
        float4* cs4 = (float4*)smf;
        const float4* gc4 = (const float4*)(g_coef + (size_t)m0 * NLOG);
        for (int i = tid; i < 128 * NLOG / 4; i += 256) cs4[i] = gc4[i];
    }
    __syncthreads();

#pragma unroll
    for (int mt = 0; mt < 4; mt++) {
#pragma unroll
        for (int half = 0; half < 2; half++) {
            const int lrow = wm * 64 + mt * 16 + lr + half * 8;
            const int t = m0 + lrow;
            const float* cc = smf + lrow * NLOG;
            float R[16];
#pragma unroll
            for (int i = 0; i < 16; i++) R[i] = cc[8 + i];
            const float hp0 = cc[4], hp1 = cc[5], hp2 = cc[6], hp3 = cc[7];
            const float* xb = x + (size_t)t * KDIM;
            float* ob = out + (size_t)t * KDIM;
#pragma unroll
            for (int nt = 0; nt < 4; nt++) {
                const int col = n0 + wn * 32 + nt * 8 + lc * 2;
                const float f0 = c[mt][nt][half * 2]     + Wb[col];
                const float f1 = c[mt][nt][half * 2 + 1] + Wb[col + 1];
                float2 xv0 = *(const float2*)(xb + col);
                float2 xv1 = *(const float2*)(xb + CN + col);
                float2 xv2 = *(const float2*)(xb + 2 * CN + col);
                float2 xv3 = *(const float2*)(xb + 3 * CN + col);
                const float hps[4] = {hp0, hp1, hp2, hp3};
#pragma unroll
                for (int o = 0; o < 4; o++) {
                    float2 r;
                    r.x = R[o*4]*xv0.x + R[o*4+1]*xv1.x + R[o*4+2]*xv2.x + R[o*4+3]*xv3.x + hps[o]*f0;
                    r.y = R[o*4]*xv0.y + R[o*4+1]*xv1.y + R[o*4+2]*xv2.y + R[o*4+3]*xv3.y + hps[o]*f1;
                    *(float2*)(ob + o * CN + col) = r;
                }
            }
        }
    }
}

extern "C" void kernel_launch(void* const* d_in, const int* in_sizes, int n_in,
                              void* d_out, int out_size) {
    const float* x      = (const float*)d_in[0];
    const float* phi    = (const float*)d_in[1];
    const float* b      = (const float*)d_in[2];
    const float* a_pre  = (const float*)d_in[3];
    const float* a_post = (const float*)d_in[4];
    const float* a_res  = (const float*)d_in[5];
    const float* W      = (const float*)d_in[6];
    const float* Wb     = (const float*)d_in[7];
    float* out = (float*)d_out;

    cudaFuncSetAttribute(k_gemm, cudaFuncAttributeMaxDynamicSharedMemorySize, GEMM_SMEM);
    cudaFuncSetAttribute(k_logits, cudaFuncAttributeMaxDynamicSharedMemorySize, LG_SMEM);

    k_transpose<<<dim3(CN / 32, CN / 32), dim3(32, 8)>>>(W);
    k_phiprep<<<KDIM / 32, dim3(32, 8)>>>(phi);
    k_logits<<<TOK / 32, 256, LG_SMEM>>>(x, b, a_pre, a_post, a_res);
    k_xin<<<TOK * 2, 256>>>(x);
    k_gemm<<<dim3(CN / 128, TOK / 128), 256, GEMM_SMEM>>>(x, Wb, out);
}